// round 12
// baseline (speedup 1.0000x reference)
#include <cuda_runtime.h>
#include <cuda_bf16.h>
#include <cstdint>

// Problem constants
#define Nn   10000
#define Bb   4
#define Ff   16
#define Tt   12
#define Ee   160000
#define Cc   64
#define SEG  192          // floats per (n,b) row (f*12+t)
#define SEG4 48           // float4 per (n,b) row

#define GROUP_BAR(gid) asm volatile("bar.sync %0, 64;" :: "r"((gid) + 1) : "memory")

__device__ __forceinline__ void mma_tf32(float c[4], const uint32_t a[4],
                                         uint32_t b0, uint32_t b1) {
    asm volatile(
        "mma.sync.aligned.m16n8k8.row.col.f32.tf32.tf32.f32 "
        "{%0,%1,%2,%3}, {%4,%5,%6,%7}, {%8,%9}, {%0,%1,%2,%3};"
        : "+f"(c[0]), "+f"(c[1]), "+f"(c[2]), "+f"(c[3])
        : "r"(a[0]), "r"(a[1]), "r"(a[2]), "r"(a[3]), "r"(b0), "r"(b1));
}

__device__ __forceinline__ uint32_t tf32u(float x) {
    uint32_t r;
    asm("cvt.rna.tf32.f32 %0, %1;" : "=r"(r) : "f"(x));
    return r;
}
__device__ __forceinline__ uint32_t ldsm32(const float* p) {
    return *reinterpret_cast<const uint32_t*>(p);
}

// ---------------- scratch (device globals; no allocation) ----------------
__device__ float g_Tx1[Nn * Bb * SEG];
__device__ float g_Tx2[Nn * Bb * SEG];
__device__ float g_deg[Nn];
__device__ int   g_degin[Nn];
__device__ int   g_off[Nn + 1];
__device__ int   g_cur[Nn];
__device__ int   g_srcs[Ee];

// ---------------- graph preprocessing ----------------
__global__ void k_count(const int* __restrict__ ei) {
    int e = blockIdx.x * blockDim.x + threadIdx.x;
    if (e < Ee) {
        atomicAdd(&g_deg[ei[e]], 1.0f);
        atomicAdd(&g_degin[ei[Ee + e]], 1);
    }
}

__global__ void k_scan() {
    __shared__ int part[1024];
    int t = threadIdx.x;
    const int CH = 10;
    int base = t * CH;
    int local[CH];
    int s = 0;
#pragma unroll
    for (int i = 0; i < CH; i++) {
        int idx = base + i;
        int v = (idx < Nn) ? g_degin[idx] : 0;
        local[i] = v; s += v;
    }
    part[t] = s;
    __syncthreads();
    for (int off = 1; off < 1024; off <<= 1) {
        int v = (t >= off) ? part[t - off] : 0;
        __syncthreads();
        part[t] += v;
        __syncthreads();
    }
    int pre = (t == 0) ? 0 : part[t - 1];
#pragma unroll
    for (int i = 0; i < CH; i++) {
        int idx = base + i;
        if (idx < Nn) { g_off[idx] = pre; g_cur[idx] = pre; pre += local[i]; }
    }
    if (t == 1023) g_off[Nn] = part[1023];
}

__global__ void k_fill(const int* __restrict__ ei) {
    int e = blockIdx.x * blockDim.x + threadIdx.x;
    if (e < Ee) {
        int c = ei[Ee + e];
        int p = atomicAdd(&g_cur[c], 1);
        g_srcs[p] = ei[e];
    }
}

// ---------------- Lhat via CSR gather (x's native layout) ----------------
__global__ void k_lhat1(const float* __restrict__ x, const float* __restrict__ lamp) {
    int n = blockIdx.x, j = threadIdx.x;
    int b = j / SEG4, r4 = j - b * SEG4;
    int boff = b * Nn;
    const float4* u = (const float4*)x;
    float4 acc = make_float4(0.f, 0.f, 0.f, 0.f);
    int e = g_off[n], e1 = g_off[n + 1];
    for (; e + 4 <= e1; e += 4) {
        int s0 = g_srcs[e], s1 = g_srcs[e + 1], s2 = g_srcs[e + 2], s3 = g_srcs[e + 3];
        float4 v0 = u[(boff + s0) * SEG4 + r4], v1 = u[(boff + s1) * SEG4 + r4];
        float4 v2 = u[(boff + s2) * SEG4 + r4], v3 = u[(boff + s3) * SEG4 + r4];
        acc.x += (v0.x + v1.x) + (v2.x + v3.x);
        acc.y += (v0.y + v1.y) + (v2.y + v3.y);
        acc.z += (v0.z + v1.z) + (v2.z + v3.z);
        acc.w += (v0.w + v1.w) + (v2.w + v3.w);
    }
    for (; e < e1; e++) {
        float4 v = u[(boff + g_srcs[e]) * SEG4 + r4];
        acc.x += v.x; acc.y += v.y; acc.z += v.z; acc.w += v.w;
    }
    float4 un = u[(boff + n) * SEG4 + r4];
    float c2 = 2.0f / lamp[0];
    float dn = g_deg[n];
    float4 r;
    r.x = c2 * (dn * un.x - acc.x) - un.x;
    r.y = c2 * (dn * un.y - acc.y) - un.y;
    r.z = c2 * (dn * un.z - acc.z) - un.z;
    r.w = c2 * (dn * un.w - acc.w) - un.w;
    ((float4*)g_Tx1)[(boff + n) * SEG4 + r4] = r;
}

__global__ void k_lhat2(const float* __restrict__ x, const float* __restrict__ lamp) {
    int n = blockIdx.x, j = threadIdx.x;
    int b = j / SEG4, r4 = j - b * SEG4;
    int boff = b * Nn;
    const float4* u = (const float4*)g_Tx1;
    float4 acc = make_float4(0.f, 0.f, 0.f, 0.f);
    int e = g_off[n], e1 = g_off[n + 1];
    for (; e + 4 <= e1; e += 4) {
        int s0 = g_srcs[e], s1 = g_srcs[e + 1], s2 = g_srcs[e + 2], s3 = g_srcs[e + 3];
        float4 v0 = u[(boff + s0) * SEG4 + r4], v1 = u[(boff + s1) * SEG4 + r4];
        float4 v2 = u[(boff + s2) * SEG4 + r4], v3 = u[(boff + s3) * SEG4 + r4];
        acc.x += (v0.x + v1.x) + (v2.x + v3.x);
        acc.y += (v0.y + v1.y) + (v2.y + v3.y);
        acc.z += (v0.z + v1.z) + (v2.z + v3.z);
        acc.w += (v0.w + v1.w) + (v2.w + v3.w);
    }
    for (; e < e1; e++) {
        float4 v = u[(boff + g_srcs[e]) * SEG4 + r4];
        acc.x += v.x; acc.y += v.y; acc.z += v.z; acc.w += v.w;
    }
    float4 un = u[(boff + n) * SEG4 + r4];
    float4 t0 = ((const float4*)x)[(boff + n) * SEG4 + r4];
    float c2 = 2.0f / lamp[0];
    float dn = g_deg[n];
    float4 r;
    r.x = 2.0f * (c2 * (dn * un.x - acc.x) - un.x) - t0.x;
    r.y = 2.0f * (c2 * (dn * un.y - acc.y) - un.y) - t0.y;
    r.z = 2.0f * (c2 * (dn * un.z - acc.z) - un.z) - t0.z;
    r.w = 2.0f * (c2 * (dn * un.w - acc.w) - un.w) - t0.w;
    ((float4*)g_Tx2)[(boff + n) * SEG4 + r4] = r;
}

// ---------------- fully-tensor fused kernel, TF32, M=48/node ----------------
// 5 groups x 64 threads per block (320 threads, 10 warps/SM). A planes stored
// FRAGMENT-ORDERED: 18 chunks (3 mtiles x 6 ktiles) x 32 lanes x 4 slots, so
// every A/residual fragment load is one LDS.128 (conflict-free).
// FIX vs R11: stage-0 fragment writes advance one LANE (16 floats) per row,
// not one slot (4 floats).
#define NG 5
#define S_ROWF 68
#define S_BSTR 952        // 14*68
#define GB_BASE 16640
#define GB_STRIDE 7168
#define SMEM_FLOATS (GB_BASE + NG * GB_STRIDE)   // 52480 floats = 209920 B

__global__ void __launch_bounds__(64 * NG, 1)
k_fused(const float* __restrict__ x,
        const float* __restrict__ chebW, const float* __restrict__ chebB,
        const float* __restrict__ timeW, const float* __restrict__ timeB,
        const float* __restrict__ resW,  const float* __restrict__ resB,
        const float* __restrict__ gamma, const float* __restrict__ beta,
        float* __restrict__ out)
{
    extern __shared__ float sm[];
    uint32_t* WFu = (uint32_t*)sm;
    const uint4* WF4 = (const uint4*)sm;
    float* cb  = sm + 16384;
    float* trb = sm + 16448;
    float* gma = sm + 16512;
    float* bta = sm + 16576;

    int tid = threadIdx.x;

    // --- one-time fragment-ordered tf32 weight staging ---
    for (int e = tid; e < 128 * 32; e += 64 * NG) {
        int chunk = e >> 5, ln = e & 31;
        int krow = ln & 3;
        int nh = ln >> 2;
        float w0, w1, w2, w3;
        if (chunk < 24) {
            int p = chunk >> 3, nt = chunk & 7;
            int n = nt * 8 + nh;
            int k0 = p * 16 + krow;
            w0 = chebW[k0 * 64 + n];        w1 = chebW[(k0 + 4) * 64 + n];
            w2 = chebW[(k0 + 8) * 64 + n];  w3 = chebW[(k0 + 12) * 64 + n];
        } else if (chunk < 120) {
            int q = chunk - 24;
            int d = q >> 5, p = (q >> 3) & 3, nt = q & 7;
            int n = nt * 8 + nh;
            int ci0 = p * 16 + krow;
            w0 = timeW[n * 192 + ci0 * 3 + d];
            w1 = timeW[n * 192 + (ci0 + 4) * 3 + d];
            w2 = timeW[n * 192 + (ci0 + 8) * 3 + d];
            w3 = timeW[n * 192 + (ci0 + 12) * 3 + d];
        } else {
            int nt = chunk - 120;
            int n = nt * 8 + nh;
            w0 = resW[n * 16 + krow];      w1 = resW[n * 16 + krow + 4];
            w2 = resW[n * 16 + krow + 8];  w3 = resW[n * 16 + krow + 12];
        }
        uint32_t* p = WFu + chunk * 128 + ln * 4;
        p[0] = tf32u(w0); p[1] = tf32u(w1); p[2] = tf32u(w2); p[3] = tf32u(w3);
    }
    if (tid < 64) {
        cb[tid]  = chebB[tid];
        trb[tid] = timeB[tid] + resB[tid];
        gma[tid] = gamma[tid];
        bta[tid] = beta[tid];
    }

    const int g = tid >> 6;        // group 0..NG-1 (one node each)
    const int c = tid & 63;
    const int lane = tid & 31;
    const int w01 = (tid >> 5) & 1;
    const int kq = lane & 3;       // fragment k index
    const int gr = lane >> 2;

    float* gbase = sm + GB_BASE + g * GB_STRIDE;
    float* Af    = gbase;                 // fragment-ordered: 18*128 = 2304 floats
    float* myhs  = gbase;                 // f32[48][64] overlays (3072)
    float* Sf    = gbase + 3072;          // S planes (3808), row-major
    float* ps    = gbase + 6880;
    float* pq    = gbase + 6976;
    float* mymu  = gbase + 7072;
    float* myrs  = gbase + 7120;

    // --- stage-0 per-thread slot mapping & fragment write bases ---
    // slot i owns float4 j4 of batch b of the node row; per plane kk, its 4
    // values (rows r = 12b+tb+e, col f) land at lane (rho&7)*4+(f&3) + e*... :
    // successive rows -> successive lanes -> +16 floats per e.
    int sgb[3];              // gather/global base: (b*Nn)*48 + j4
    int abase[3][3];         // fragment write base per (slot, kk)
#pragma unroll
    for (int i = 0; i < 3; i++) {
        int idx = c + 64 * i;                 // 0..191
        int b = idx / 48, j4 = idx - b * 48;
        int f = j4 / 3, tb = (j4 - f * 3) * 4;
        sgb[i] = b * Nn * SEG4 + j4;
        int rbase = 12 * b + tb;
        int mt = rbase >> 4;
        int rho = rbase & 15;
        int lanebase = (rho & 7) * 4 + (f & 3);
        int slot = (rho >> 3) + 2 * ((f >> 2) & 1);
#pragma unroll
        for (int kk = 0; kk < 3; kk++) {
            int jj = kk * 16 + f;
            int ach = mt * 6 + (jj >> 3);
            abase[i][kk] = ach * 128 + lanebase * 4 + slot;
        }
    }

    // precomputed per-thread fragment row mapping for S reads / hs rows
    int offS0[3], offS1[3], rr0[3], rr1[3];
#pragma unroll
    for (int mt = 0; mt < 3; mt++) {
        int r0 = mt * 16 + gr, r1 = r0 + 8;
        int b0 = r0 / 12, t0 = r0 - b0 * 12;
        int b1 = r1 / 12, t1 = r1 - b1 * 12;
        offS0[mt] = b0 * S_BSTR + t0 * S_ROWF;
        offS1[mt] = b1 * S_BSTR + t1 * S_ROWF;
        rr0[mt] = r0; rr1[mt] = r1;
    }

    // one-time per-group init: S zero-pad rows 0 and 13 per b-plane
    {
#pragma unroll
        for (int b = 0; b < 4; b++) {
            Sf[b * S_BSTR + 0 * S_ROWF + c]  = 0.f;
            Sf[b * S_BSTR + 13 * S_ROWF + c] = 0.f;
        }
    }
    __syncthreads();

    for (int n = blockIdx.x * NG + g; n < Nn; n += 148 * NG) {

        // ---- Stage 0: load x/Tx1/Tx2 -> tf32 fragment-ordered A ----
        {
            const float4* x4  = (const float4*)x;
            const float4* t14 = (const float4*)g_Tx1;
            const float4* t24 = (const float4*)g_Tx2;
            const int nb = n * SEG4;
#pragma unroll
            for (int i = 0; i < 3; i++) {
                float4 v0 = x4[sgb[i] + nb];
                float4 v1 = t14[sgb[i] + nb];
                float4 v2 = t24[sgb[i] + nb];
                float* d0 = Af + abase[i][0];
                d0[0]  = __uint_as_float(tf32u(v0.x));
                d0[16] = __uint_as_float(tf32u(v0.y));
                d0[32] = __uint_as_float(tf32u(v0.z));
                d0[48] = __uint_as_float(tf32u(v0.w));
                float* d1 = Af + abase[i][1];
                d1[0]  = __uint_as_float(tf32u(v1.x));
                d1[16] = __uint_as_float(tf32u(v1.y));
                d1[32] = __uint_as_float(tf32u(v1.z));
                d1[48] = __uint_as_float(tf32u(v1.w));
                float* d2 = Af + abase[i][2];
                d2[0]  = __uint_as_float(tf32u(v2.x));
                d2[16] = __uint_as_float(tf32u(v2.y));
                d2[32] = __uint_as_float(tf32u(v2.z));
                d2[48] = __uint_as_float(tf32u(v2.w));
            }
        }
        GROUP_BAR(g);

        // ---- Stage A: cheb projection (M=48, K=48) -> relu -> S ----
        {
            float CA[3][4][4];
#pragma unroll
            for (int mt = 0; mt < 3; mt++)
#pragma unroll
                for (int nt = 0; nt < 4; nt++)
#pragma unroll
                    for (int r = 0; r < 4; r++) CA[mt][nt][r] = 0.f;

#pragma unroll
            for (int p = 0; p < 3; p++) {
                uint32_t aA[2][3][4];
#pragma unroll
                for (int h = 0; h < 2; h++) {
                    int k8 = 2 * p + h;
#pragma unroll
                    for (int mt = 0; mt < 3; mt++) {
                        uint4 a = *(const uint4*)(Af + (mt * 6 + k8) * 128 + lane * 4);
                        aA[h][mt][0] = a.x; aA[h][mt][1] = a.y;
                        aA[h][mt][2] = a.z; aA[h][mt][3] = a.w;
                    }
                }
#pragma unroll
                for (int ntl = 0; ntl < 4; ntl++) {
                    uint4 wb = WF4[(p * 8 + w01 * 4 + ntl) * 32 + lane];
#pragma unroll
                    for (int mt = 0; mt < 3; mt++) {
                        mma_tf32(CA[mt][ntl], aA[0][mt], wb.x, wb.y);
                        mma_tf32(CA[mt][ntl], aA[1][mt], wb.z, wb.w);
                    }
                }
            }
            // epilogue: bias + relu -> tf32 -> S at tpos = t+1 (row-major)
#pragma unroll
            for (int mt = 0; mt < 3; mt++) {
#pragma unroll
                for (int ntl = 0; ntl < 4; ntl++) {
                    int ccol = w01 * 32 + ntl * 8 + kq * 2;
                    float b0 = cb[ccol], b1 = cb[ccol + 1];
                    Sf[offS0[mt] + S_ROWF + ccol] =
                        __uint_as_float(tf32u(fmaxf(CA[mt][ntl][0] + b0, 0.f)));
                    Sf[offS0[mt] + S_ROWF + ccol + 1] =
                        __uint_as_float(tf32u(fmaxf(CA[mt][ntl][1] + b1, 0.f)));
                    Sf[offS1[mt] + S_ROWF + ccol] =
                        __uint_as_float(tf32u(fmaxf(CA[mt][ntl][2] + b0, 0.f)));
                    Sf[offS1[mt] + S_ROWF + ccol + 1] =
                        __uint_as_float(tf32u(fmaxf(CA[mt][ntl][3] + b1, 0.f)));
                }
            }
        }
        GROUP_BAR(g);

        // ---- Stage B: conv (3 shifted GEMMs, K=64) + residual (K=16) ----
        float CB[3][4][4];
#pragma unroll
        for (int mt = 0; mt < 3; mt++)
#pragma unroll
            for (int nt = 0; nt < 4; nt++)
#pragma unroll
                for (int r = 0; r < 4; r++) CB[mt][nt][r] = 0.f;

#pragma unroll
        for (int d = 0; d < 3; d++) {
#pragma unroll
            for (int p = 0; p < 4; p++) {
                uint32_t aS[2][3][4];
#pragma unroll
                for (int h = 0; h < 2; h++) {
                    int kcol = (2 * p + h) * 8 + kq;
#pragma unroll
                    for (int mt = 0; mt < 3; mt++) {
                        int o0 = offS0[mt] + d * S_ROWF;
                        int o1 = offS1[mt] + d * S_ROWF;
                        aS[h][mt][0] = ldsm32(Sf + o0 + kcol);
                        aS[h][mt][1] = ldsm32(Sf + o1 + kcol);
                        aS[h][mt][2] = ldsm32(Sf + o0 + kcol + 4);
                        aS[h][mt][3] = ldsm32(Sf + o1 + kcol + 4);
                    }
                }
#pragma unroll
                for (int ntl = 0; ntl < 4; ntl++) {
                    uint4 wb = WF4[(24 + d * 32 + p * 8 + w01 * 4 + ntl) * 32 + lane];
#pragma unroll
                    for (int mt = 0; mt < 3; mt++) {
                        mma_tf32(CB[mt][ntl], aS[0][mt], wb.x, wb.y);
                        mma_tf32(CB[mt][ntl], aS[1][mt], wb.z, wb.w);
                    }
                }
            }
        }
        // residual GEMM: A = x plane (fragment chunks mt*6 + {0,1})
        {
            uint32_t aR[2][3][4];
#pragma unroll
            for (int h = 0; h < 2; h++) {
#pragma unroll
                for (int mt = 0; mt < 3; mt++) {
                    uint4 a = *(const uint4*)(Af + (mt * 6 + h) * 128 + lane * 4);
                    aR[h][mt][0] = a.x; aR[h][mt][1] = a.y;
                    aR[h][mt][2] = a.z; aR[h][mt][3] = a.w;
                }
            }
#pragma unroll
            for (int ntl = 0; ntl < 4; ntl++) {
                uint4 wb = WF4[(120 + w01 * 4 + ntl) * 32 + lane];
#pragma unroll
                for (int mt = 0; mt < 3; mt++) {
                    mma_tf32(CB[mt][ntl], aR[0][mt], wb.x, wb.y);
                    mma_tf32(CB[mt][ntl], aR[1][mt], wb.z, wb.w);
                }
            }
        }
        GROUP_BAR(g);   // A-region reads done; safe to overlay with myhs

        // ---- Stage B epilogue: bias+relu -> myhs + quad-partial LN stats ----
        {
#pragma unroll
            for (int mt = 0; mt < 3; mt++) {
                float s0 = 0.f, q0 = 0.f, s1 = 0.f, q1 = 0.f;
#pragma unroll
                for (int ntl = 0; ntl < 4; ntl++) {
                    int ccol = w01 * 32 + ntl * 8 + kq * 2;
                    float b0 = trb[ccol], b1 = trb[ccol + 1];
                    float v0 = fmaxf(CB[mt][ntl][0] + b0, 0.f);
                    float v1 = fmaxf(CB[mt][ntl][1] + b1, 0.f);
                    float v2 = fmaxf(CB[mt][ntl][2] + b0, 0.f);
                    float v3 = fmaxf(CB[mt][ntl][3] + b1, 0.f);
                    *(float2*)(myhs + rr0[mt] * 64 + ccol) = make_float2(v0, v1);
                    *(float2*)(myhs + rr1[mt] * 64 + ccol) = make_float2(v2, v3);
                    s0 += v0 + v1; q0 += v0 * v0 + v1 * v1;
                    s1 += v2 + v3; q1 += v2 * v2 + v3 * v3;
                }
                s0 += __shfl_xor_sync(0xffffffffu, s0, 1);
                s0 += __shfl_xor_sync(0xffffffffu, s0, 2);
                q0 += __shfl_xor_sync(0xffffffffu, q0, 1);
                q0 += __shfl_xor_sync(0xffffffffu, q0, 2);
                s1 += __shfl_xor_sync(0xffffffffu, s1, 1);
                s1 += __shfl_xor_sync(0xffffffffu, s1, 2);
                q1 += __shfl_xor_sync(0xffffffffu, q1, 1);
                q1 += __shfl_xor_sync(0xffffffffu, q1, 2);
                if (kq == 0) {
                    ps[w01 * 48 + rr0[mt]] = s0;
                    pq[w01 * 48 + rr0[mt]] = q0;
                    ps[w01 * 48 + rr1[mt]] = s1;
                    pq[w01 * 48 + rr1[mt]] = q1;
                }
            }
        }
        GROUP_BAR(g);

        // ---- LN stats combine (48 rows) ----
        if (c < 48) {
            float s = ps[c] + ps[48 + c];
            float q2 = pq[c] + pq[48 + c];
            float mu = s * (1.0f / 64.0f);
            float var = q2 * (1.0f / 64.0f) - mu * mu;
            mymu[c] = mu;
            myrs[c] = rsqrtf(var + 1e-5f);
        }
        GROUP_BAR(g);

        // ---- normalize + write out (B,N,C,T) ----
        {
            float ga = gma[c], be = bta[c];
#pragma unroll
            for (int b = 0; b < 4; b++) {
                float o[12];
#pragma unroll
                for (int t = 0; t < 12; t++) {
                    int r = b * 12 + t;
                    o[t] = (myhs[r * 64 + c] - mymu[r]) * myrs[r] * ga + be;
                }
                float* op = out + (((size_t)b * Nn + n) * 64 + c) * 12;
                float4* op4 = (float4*)op;
                op4[0] = make_float4(o[0], o[1], o[2],  o[3]);
                op4[1] = make_float4(o[4], o[5], o[6],  o[7]);
                op4[2] = make_float4(o[8], o[9], o[10], o[11]);
            }
        }
        GROUP_BAR(g);   // myhs reads done before next tile's stage-0 A writes
    }
}

// ---------------- launcher ----------------
extern "C" void kernel_launch(void* const* d_in, const int* in_sizes, int n_in,
                              void* d_out, int out_size)
{
    const float* x     = (const float*)d_in[0];
    const int*   ei    = (const int*)d_in[1];
    const float* lam   = (const float*)d_in[2];
    const float* chebW = (const float*)d_in[3];
    const float* chebB = (const float*)d_in[4];
    const float* timeW = (const float*)d_in[5];
    const float* timeB = (const float*)d_in[6];
    const float* resW  = (const float*)d_in[7];
    const float* resB  = (const float*)d_in[8];
    const float* gma   = (const float*)d_in[9];
    const float* bta   = (const float*)d_in[10];
    float* out = (float*)d_out;

    // zero degree arrays via capturable async memsets
    void* pdeg = nullptr; void* pdegin = nullptr;
    cudaGetSymbolAddress(&pdeg, g_deg);
    cudaGetSymbolAddress(&pdegin, g_degin);
    cudaMemsetAsync(pdeg, 0, Nn * sizeof(float));
    cudaMemsetAsync(pdegin, 0, Nn * sizeof(int));

    k_count<<<(Ee + 255) / 256, 256>>>(ei);
    k_scan<<<1, 1024>>>();
    k_fill<<<(Ee + 255) / 256, 256>>>(ei);
    k_lhat1<<<Nn, 192>>>(x, lam);
    k_lhat2<<<Nn, 192>>>(x, lam);

    cudaFuncSetAttribute(k_fused, cudaFuncAttributeMaxDynamicSharedMemorySize,
                         SMEM_FLOATS * 4);
    // 148 blocks x 320 threads: 1 block/SM, 5 node-groups per block
    k_fused<<<148, 64 * NG, SMEM_FLOATS * 4>>>(x, chebW, chebB, timeW, timeB,
                                               resW, resB, gma, bta, out);
}

// round 13
// speedup vs baseline: 1.0617x; 1.0617x over previous
#include <cuda_runtime.h>
#include <cuda_bf16.h>
#include <cstdint>

// Problem constants
#define Nn   10000
#define Bb   4
#define Ff   16
#define Tt   12
#define Ee   160000
#define Cc   64
#define SEG  192          // floats per (n,b) row (f*12+t)
#define SEG4 48           // float4 per (n,b) row

#define GROUP_BAR(gid) asm volatile("bar.sync %0, 64;" :: "r"((gid) + 1) : "memory")

__device__ __forceinline__ void mma_tf32(float c[4], const uint32_t a[4],
                                         uint32_t b0, uint32_t b1) {
    asm volatile(
        "mma.sync.aligned.m16n8k8.row.col.f32.tf32.tf32.f32 "
        "{%0,%1,%2,%3}, {%4,%5,%6,%7}, {%8,%9}, {%0,%1,%2,%3};"
        : "+f"(c[0]), "+f"(c[1]), "+f"(c[2]), "+f"(c[3])
        : "r"(a[0]), "r"(a[1]), "r"(a[2]), "r"(a[3]), "r"(b0), "r"(b1));
}

__device__ __forceinline__ uint32_t tf32u(float x) {
    uint32_t r;
    asm("cvt.rna.tf32.f32 %0, %1;" : "=r"(r) : "f"(x));
    return r;
}
__device__ __forceinline__ uint32_t ldsm32(const float* p) {
    return *reinterpret_cast<const uint32_t*>(p);
}

// ---------------- scratch (device globals; no allocation) ----------------
__device__ float g_Tx1[Nn * Bb * SEG];
__device__ float g_Tx2[Nn * Bb * SEG];
__device__ float g_deg[Nn];
__device__ int   g_degin[Nn];
__device__ int   g_off[Nn + 1];
__device__ int   g_cur[Nn];
__device__ int   g_srcs[Ee];

// ---------------- graph preprocessing ----------------
__global__ void k_count(const int* __restrict__ ei) {
    int e = blockIdx.x * blockDim.x + threadIdx.x;
    if (e < Ee) {
        atomicAdd(&g_deg[ei[e]], 1.0f);
        atomicAdd(&g_degin[ei[Ee + e]], 1);
    }
}

__global__ void k_scan() {
    __shared__ int part[1024];
    int t = threadIdx.x;
    const int CH = 10;
    int base = t * CH;
    int local[CH];
    int s = 0;
#pragma unroll
    for (int i = 0; i < CH; i++) {
        int idx = base + i;
        int v = (idx < Nn) ? g_degin[idx] : 0;
        local[i] = v; s += v;
    }
    part[t] = s;
    __syncthreads();
    for (int off = 1; off < 1024; off <<= 1) {
        int v = (t >= off) ? part[t - off] : 0;
        __syncthreads();
        part[t] += v;
        __syncthreads();
    }
    int pre = (t == 0) ? 0 : part[t - 1];
#pragma unroll
    for (int i = 0; i < CH; i++) {
        int idx = base + i;
        if (idx < Nn) { g_off[idx] = pre; g_cur[idx] = pre; pre += local[i]; }
    }
    if (t == 1023) g_off[Nn] = part[1023];
}

__global__ void k_fill(const int* __restrict__ ei) {
    int e = blockIdx.x * blockDim.x + threadIdx.x;
    if (e < Ee) {
        int c = ei[Ee + e];
        int p = atomicAdd(&g_cur[c], 1);
        g_srcs[p] = ei[e];
    }
}

// ---------------- Lhat via CSR gather (x's native layout) ----------------
__global__ void k_lhat1(const float* __restrict__ x, const float* __restrict__ lamp) {
    int n = blockIdx.x, j = threadIdx.x;
    int b = j / SEG4, r4 = j - b * SEG4;
    int boff = b * Nn;
    const float4* u = (const float4*)x;
    float4 acc = make_float4(0.f, 0.f, 0.f, 0.f);
    int e = g_off[n], e1 = g_off[n + 1];
    for (; e + 4 <= e1; e += 4) {
        int s0 = g_srcs[e], s1 = g_srcs[e + 1], s2 = g_srcs[e + 2], s3 = g_srcs[e + 3];
        float4 v0 = u[(boff + s0) * SEG4 + r4], v1 = u[(boff + s1) * SEG4 + r4];
        float4 v2 = u[(boff + s2) * SEG4 + r4], v3 = u[(boff + s3) * SEG4 + r4];
        acc.x += (v0.x + v1.x) + (v2.x + v3.x);
        acc.y += (v0.y + v1.y) + (v2.y + v3.y);
        acc.z += (v0.z + v1.z) + (v2.z + v3.z);
        acc.w += (v0.w + v1.w) + (v2.w + v3.w);
    }
    for (; e < e1; e++) {
        float4 v = u[(boff + g_srcs[e]) * SEG4 + r4];
        acc.x += v.x; acc.y += v.y; acc.z += v.z; acc.w += v.w;
    }
    float4 un = u[(boff + n) * SEG4 + r4];
    float c2 = 2.0f / lamp[0];
    float dn = g_deg[n];
    float4 r;
    r.x = c2 * (dn * un.x - acc.x) - un.x;
    r.y = c2 * (dn * un.y - acc.y) - un.y;
    r.z = c2 * (dn * un.z - acc.z) - un.z;
    r.w = c2 * (dn * un.w - acc.w) - un.w;
    ((float4*)g_Tx1)[(boff + n) * SEG4 + r4] = r;
}

__global__ void k_lhat2(const float* __restrict__ x, const float* __restrict__ lamp) {
    int n = blockIdx.x, j = threadIdx.x;
    int b = j / SEG4, r4 = j - b * SEG4;
    int boff = b * Nn;
    const float4* u = (const float4*)g_Tx1;
    float4 acc = make_float4(0.f, 0.f, 0.f, 0.f);
    int e = g_off[n], e1 = g_off[n + 1];
    for (; e + 4 <= e1; e += 4) {
        int s0 = g_srcs[e], s1 = g_srcs[e + 1], s2 = g_srcs[e + 2], s3 = g_srcs[e + 3];
        float4 v0 = u[(boff + s0) * SEG4 + r4], v1 = u[(boff + s1) * SEG4 + r4];
        float4 v2 = u[(boff + s2) * SEG4 + r4], v3 = u[(boff + s3) * SEG4 + r4];
        acc.x += (v0.x + v1.x) + (v2.x + v3.x);
        acc.y += (v0.y + v1.y) + (v2.y + v3.y);
        acc.z += (v0.z + v1.z) + (v2.z + v3.z);
        acc.w += (v0.w + v1.w) + (v2.w + v3.w);
    }
    for (; e < e1; e++) {
        float4 v = u[(boff + g_srcs[e]) * SEG4 + r4];
        acc.x += v.x; acc.y += v.y; acc.z += v.z; acc.w += v.w;
    }
    float4 un = u[(boff + n) * SEG4 + r4];
    float4 t0 = ((const float4*)x)[(boff + n) * SEG4 + r4];
    float c2 = 2.0f / lamp[0];
    float dn = g_deg[n];
    float4 r;
    r.x = 2.0f * (c2 * (dn * un.x - acc.x) - un.x) - t0.x;
    r.y = 2.0f * (c2 * (dn * un.y - acc.y) - un.y) - t0.y;
    r.z = 2.0f * (c2 * (dn * un.z - acc.z) - un.z) - t0.z;
    r.w = 2.0f * (c2 * (dn * un.w - acc.w) - un.w) - t0.w;
    ((float4*)g_Tx2)[(boff + n) * SEG4 + r4] = r;
}

// ---------------- fully-tensor fused kernel, TF32, M=48 per node ----------------
// R9 configuration (best known: 217.3us): 4 groups x 64 threads, row-major
// A/S planes. Delta vs R9: Stage-A epilogue stores vectorized to STS.64.
#define A_ROWF 52
#define A_BSTR 624        // 12*52
#define S_ROWF 68
#define S_BSTR 952        // 14*68
#define GB_BASE 16640
#define GB_STRIDE 7168
#define SMEM_FLOATS (GB_BASE + 4 * GB_STRIDE)   // 45312 floats = 181248 B

__global__ void __launch_bounds__(256, 1)
k_fused(const float* __restrict__ x,
        const float* __restrict__ chebW, const float* __restrict__ chebB,
        const float* __restrict__ timeW, const float* __restrict__ timeB,
        const float* __restrict__ resW,  const float* __restrict__ resB,
        const float* __restrict__ gamma, const float* __restrict__ beta,
        float* __restrict__ out)
{
    extern __shared__ float sm[];
    uint32_t* WFu = (uint32_t*)sm;
    const uint4* WF4 = (const uint4*)sm;
    float* cb  = sm + 16384;
    float* trb = sm + 16448;
    float* gma = sm + 16512;
    float* bta = sm + 16576;

    int tid = threadIdx.x;

    // --- one-time fragment-ordered tf32 weight staging ---
    for (int e = tid; e < 128 * 32; e += 256) {
        int chunk = e >> 5, ln = e & 31;
        int krow = ln & 3;
        int nh = ln >> 2;
        float w0, w1, w2, w3;
        if (chunk < 24) {              // cheb: K=48, pairs p=0..2, nt 0..7
            int p = chunk >> 3, nt = chunk & 7;
            int n = nt * 8 + nh;
            int k0 = p * 16 + krow;
            w0 = chebW[k0 * 64 + n];        w1 = chebW[(k0 + 4) * 64 + n];
            w2 = chebW[(k0 + 8) * 64 + n];  w3 = chebW[(k0 + 12) * 64 + n];
        } else if (chunk < 120) {      // conv: d(3) x pairs(4) x nt(8)
            int q = chunk - 24;
            int d = q >> 5, p = (q >> 3) & 3, nt = q & 7;
            int n = nt * 8 + nh;
            int ci0 = p * 16 + krow;
            w0 = timeW[n * 192 + ci0 * 3 + d];
            w1 = timeW[n * 192 + (ci0 + 4) * 3 + d];
            w2 = timeW[n * 192 + (ci0 + 8) * 3 + d];
            w3 = timeW[n * 192 + (ci0 + 12) * 3 + d];
        } else {                       // residual: K=16, 1 pair
            int nt = chunk - 120;
            int n = nt * 8 + nh;
            w0 = resW[n * 16 + krow];      w1 = resW[n * 16 + krow + 4];
            w2 = resW[n * 16 + krow + 8];  w3 = resW[n * 16 + krow + 12];
        }
        uint32_t* p = WFu + chunk * 128 + ln * 4;
        p[0] = tf32u(w0); p[1] = tf32u(w1); p[2] = tf32u(w2); p[3] = tf32u(w3);
    }
    if (tid < 64) {
        cb[tid]  = chebB[tid];
        trb[tid] = timeB[tid] + resB[tid];
        gma[tid] = gamma[tid];
        bta[tid] = beta[tid];
    }

    const int g = tid >> 6;        // group 0..3 (one node each)
    const int c = tid & 63;
    const int lane = tid & 31;
    const int w01 = (tid >> 5) & 1;
    const int kq = lane & 3;       // fragment k index
    const int gr = lane >> 2;

    float* gbase = sm + GB_BASE + g * GB_STRIDE;
    float* Af    = gbase;                 // A planes (2496) -- myhs overlays
    float* myhs  = gbase;                 // f32[48][64]
    float* Sf    = gbase + 3072;          // S planes (3808)
    float* ps    = gbase + 6880;
    float* pq    = gbase + 6976;
    float* mymu  = gbase + 7072;
    float* myrs  = gbase + 7120;

    // precomputed per-thread fragment row mapping
    int offA0[3], offA1[3], offS0[3], offS1[3], rr0[3], rr1[3];
#pragma unroll
    for (int mt = 0; mt < 3; mt++) {
        int r0 = mt * 16 + gr, r1 = r0 + 8;
        int b0 = r0 / 12, t0 = r0 - b0 * 12;
        int b1 = r1 / 12, t1 = r1 - b1 * 12;
        offA0[mt] = b0 * A_BSTR + t0 * A_ROWF;
        offA1[mt] = b1 * A_BSTR + t1 * A_ROWF;
        offS0[mt] = b0 * S_BSTR + t0 * S_ROWF;
        offS1[mt] = b1 * S_BSTR + t1 * S_ROWF;
        rr0[mt] = r0; rr1[mt] = r1;
    }

    // one-time per-group init: S zero-pad rows 0 and 13 per b-plane
    {
#pragma unroll
        for (int b = 0; b < 4; b++) {
            Sf[b * S_BSTR + 0 * S_ROWF + c]  = 0.f;
            Sf[b * S_BSTR + 13 * S_ROWF + c] = 0.f;
        }
    }
    __syncthreads();

    for (int n = blockIdx.x * 4 + g; n < Nn; n += 592) {

        // ---- Stage 0: vectorized loads of x/Tx1/Tx2 -> tf32 A planes ----
        {
            const float* srcs[3] = { x, g_Tx1, g_Tx2 };
#pragma unroll
            for (int rep = 0; rep < 9; rep++) {
                int i = rep * 64 + c;           // 0..575
                int kkb = i / 48, j = i - kkb * 48;
                int kk = kkb >> 2, b = kkb & 3;
                int f = j / 3, t0 = (j - f * 3) * 4;
                const float4* src4 = (const float4*)
                    (srcs[kk] + (size_t)(b * Nn + n) * SEG);
                float4 v = src4[j];
                float* dst = Af + b * A_BSTR + t0 * A_ROWF + kk * 16 + f;
                dst[0]          = __uint_as_float(tf32u(v.x));
                dst[A_ROWF]     = __uint_as_float(tf32u(v.y));
                dst[2 * A_ROWF] = __uint_as_float(tf32u(v.z));
                dst[3 * A_ROWF] = __uint_as_float(tf32u(v.w));
            }
        }
        GROUP_BAR(g);

        // ---- Stage A: cheb projection (M=48, K=48) -> relu -> S ----
        {
            float CA[3][4][4];
#pragma unroll
            for (int mt = 0; mt < 3; mt++)
#pragma unroll
                for (int nt = 0; nt < 4; nt++)
#pragma unroll
                    for (int r = 0; r < 4; r++) CA[mt][nt][r] = 0.f;

#pragma unroll
            for (int p = 0; p < 3; p++) {
                uint32_t aA[2][3][4];
#pragma unroll
                for (int h = 0; h < 2; h++) {
                    int kcol = (2 * p + h) * 8 + kq;
#pragma unroll
                    for (int mt = 0; mt < 3; mt++) {
                        aA[h][mt][0] = ldsm32(Af + offA0[mt] + kcol);
                        aA[h][mt][1] = ldsm32(Af + offA1[mt] + kcol);
                        aA[h][mt][2] = ldsm32(Af + offA0[mt] + kcol + 4);
                        aA[h][mt][3] = ldsm32(Af + offA1[mt] + kcol + 4);
                    }
                }
#pragma unroll
                for (int ntl = 0; ntl < 4; ntl++) {
                    uint4 wb = WF4[(p * 8 + w01 * 4 + ntl) * 32 + lane];
#pragma unroll
                    for (int mt = 0; mt < 3; mt++) {
                        mma_tf32(CA[mt][ntl], aA[0][mt], wb.x, wb.y);
                        mma_tf32(CA[mt][ntl], aA[1][mt], wb.z, wb.w);
                    }
                }
            }
            // epilogue: bias + relu -> tf32 -> S at tpos = t+1 (STS.64 pairs)
#pragma unroll
            for (int mt = 0; mt < 3; mt++) {
#pragma unroll
                for (int ntl = 0; ntl < 4; ntl++) {
                    int ccol = w01 * 32 + ntl * 8 + kq * 2;
                    float b0 = cb[ccol], b1 = cb[ccol + 1];
                    float2 p01 = make_float2(
                        __uint_as_float(tf32u(fmaxf(CA[mt][ntl][0] + b0, 0.f))),
                        __uint_as_float(tf32u(fmaxf(CA[mt][ntl][1] + b1, 0.f))));
                    *(float2*)(Sf + offS0[mt] + S_ROWF + ccol) = p01;
                    float2 p23 = make_float2(
                        __uint_as_float(tf32u(fmaxf(CA[mt][ntl][2] + b0, 0.f))),
                        __uint_as_float(tf32u(fmaxf(CA[mt][ntl][3] + b1, 0.f))));
                    *(float2*)(Sf + offS1[mt] + S_ROWF + ccol) = p23;
                }
            }
        }
        GROUP_BAR(g);

        // ---- Stage B: conv (3 shifted GEMMs, K=64 each) + residual (K=16) ----
        float CB[3][4][4];
#pragma unroll
        for (int mt = 0; mt < 3; mt++)
#pragma unroll
            for (int nt = 0; nt < 4; nt++)
#pragma unroll
                for (int r = 0; r < 4; r++) CB[mt][nt][r] = 0.f;

#pragma unroll
        for (int d = 0; d < 3; d++) {
#pragma unroll
            for (int p = 0; p < 4; p++) {
                uint32_t aS[2][3][4];
#pragma unroll
                for (int h = 0; h < 2; h++) {
                    int kcol = (2 * p + h) * 8 + kq;
#pragma unroll
                    for (int mt = 0; mt < 3; mt++) {
                        int o0 = offS0[mt] + d * S_ROWF;
                        int o1 = offS1[mt] + d * S_ROWF;
                        aS[h][mt][0] = ldsm32(Sf + o0 + kcol);
                        aS[h][mt][1] = ldsm32(Sf + o1 + kcol);
                        aS[h][mt][2] = ldsm32(Sf + o0 + kcol + 4);
                        aS[h][mt][3] = ldsm32(Sf + o1 + kcol + 4);
                    }
                }
#pragma unroll
                for (int ntl = 0; ntl < 4; ntl++) {
                    uint4 wb = WF4[(24 + d * 32 + p * 8 + w01 * 4 + ntl) * 32 + lane];
#pragma unroll
                    for (int mt = 0; mt < 3; mt++) {
                        mma_tf32(CB[mt][ntl], aS[0][mt], wb.x, wb.y);
                        mma_tf32(CB[mt][ntl], aS[1][mt], wb.z, wb.w);
                    }
                }
            }
        }
        // residual GEMM: A = x plane (A cols 0..15)
        {
            uint32_t aR[2][3][4];
#pragma unroll
            for (int h = 0; h < 2; h++) {
                int kcol = h * 8 + kq;
#pragma unroll
                for (int mt = 0; mt < 3; mt++) {
                    aR[h][mt][0] = ldsm32(Af + offA0[mt] + kcol);
                    aR[h][mt][1] = ldsm32(Af + offA1[mt] + kcol);
                    aR[h][mt][2] = ldsm32(Af + offA0[mt] + kcol + 4);
                    aR[h][mt][3] = ldsm32(Af + offA1[mt] + kcol + 4);
                }
            }
#pragma unroll
            for (int ntl = 0; ntl < 4; ntl++) {
                uint4 wb = WF4[(120 + w01 * 4 + ntl) * 32 + lane];
#pragma unroll
                for (int mt = 0; mt < 3; mt++) {
                    mma_tf32(CB[mt][ntl], aR[0][mt], wb.x, wb.y);
                    mma_tf32(CB[mt][ntl], aR[1][mt], wb.z, wb.w);
                }
            }
        }
        GROUP_BAR(g);   // A-region reads done; safe to overlay with myhs

        // ---- Stage B epilogue: bias+relu -> myhs + quad-partial LN stats ----
        {
#pragma unroll
            for (int mt = 0; mt < 3; mt++) {
                float s0 = 0.f, q0 = 0.f, s1 = 0.f, q1 = 0.f;
#pragma unroll
                for (int ntl = 0; ntl < 4; ntl++) {
                    int ccol = w01 * 32 + ntl * 8 + kq * 2;
                    float b0 = trb[ccol], b1 = trb[ccol + 1];
                    float v0 = fmaxf(CB[mt][ntl][0] + b0, 0.f);
                    float v1 = fmaxf(CB[mt][ntl][1] + b1, 0.f);
                    float v2 = fmaxf(CB[mt][ntl][2] + b0, 0.f);
                    float v3 = fmaxf(CB[mt][ntl][3] + b1, 0.f);
                    *(float2*)(myhs + rr0[mt] * 64 + ccol) = make_float2(v0, v1);
                    *(float2*)(myhs + rr1[mt] * 64 + ccol) = make_float2(v2, v3);
                    s0 += v0 + v1; q0 += v0 * v0 + v1 * v1;
                    s1 += v2 + v3; q1 += v2 * v2 + v3 * v3;
                }
                s0 += __shfl_xor_sync(0xffffffffu, s0, 1);
                s0 += __shfl_xor_sync(0xffffffffu, s0, 2);
                q0 += __shfl_xor_sync(0xffffffffu, q0, 1);
                q0 += __shfl_xor_sync(0xffffffffu, q0, 2);
                s1 += __shfl_xor_sync(0xffffffffu, s1, 1);
                s1 += __shfl_xor_sync(0xffffffffu, s1, 2);
                q1 += __shfl_xor_sync(0xffffffffu, q1, 1);
                q1 += __shfl_xor_sync(0xffffffffu, q1, 2);
                if (kq == 0) {
                    ps[w01 * 48 + rr0[mt]] = s0;
                    pq[w01 * 48 + rr0[mt]] = q0;
                    ps[w01 * 48 + rr1[mt]] = s1;
                    pq[w01 * 48 + rr1[mt]] = q1;
                }
            }
        }
        GROUP_BAR(g);

        // ---- LN stats combine (48 rows) ----
        if (c < 48) {
            float s = ps[c] + ps[48 + c];
            float q2 = pq[c] + pq[48 + c];
            float mu = s * (1.0f / 64.0f);
            float var = q2 * (1.0f / 64.0f) - mu * mu;
            mymu[c] = mu;
            myrs[c] = rsqrtf(var + 1e-5f);
        }
        GROUP_BAR(g);

        // ---- normalize + write out (B,N,C,T) ----
        {
            float ga = gma[c], be = bta[c];
#pragma unroll
            for (int b = 0; b < 4; b++) {
                float o[12];
#pragma unroll
                for (int t = 0; t < 12; t++) {
                    int r = b * 12 + t;
                    o[t] = (myhs[r * 64 + c] - mymu[r]) * myrs[r] * ga + be;
                }
                float* op = out + (((size_t)b * Nn + n) * 64 + c) * 12;
                float4* op4 = (float4*)op;
                op4[0] = make_float4(o[0], o[1], o[2],  o[3]);
                op4[1] = make_float4(o[4], o[5], o[6],  o[7]);
                op4[2] = make_float4(o[8], o[9], o[10], o[11]);
            }
        }
        GROUP_BAR(g);   // myhs reads done before next tile's stage-0 A writes
    }
}

// ---------------- launcher ----------------
extern "C" void kernel_launch(void* const* d_in, const int* in_sizes, int n_in,
                              void* d_out, int out_size)
{
    const float* x     = (const float*)d_in[0];
    const int*   ei    = (const int*)d_in[1];
    const float* lam   = (const float*)d_in[2];
    const float* chebW = (const float*)d_in[3];
    const float* chebB = (const float*)d_in[4];
    const float* timeW = (const float*)d_in[5];
    const float* timeB = (const float*)d_in[6];
    const float* resW  = (const float*)d_in[7];
    const float* resB  = (const float*)d_in[8];
    const float* gma   = (const float*)d_in[9];
    const float* bta   = (const float*)d_in[10];
    float* out = (float*)d_out;

    // zero degree arrays via capturable async memsets
    void* pdeg = nullptr; void* pdegin = nullptr;
    cudaGetSymbolAddress(&pdeg, g_deg);
    cudaGetSymbolAddress(&pdegin, g_degin);
    cudaMemsetAsync(pdeg, 0, Nn * sizeof(float));
    cudaMemsetAsync(pdegin, 0, Nn * sizeof(int));

    k_count<<<(Ee + 255) / 256, 256>>>(ei);
    k_scan<<<1, 1024>>>();
    k_fill<<<(Ee + 255) / 256, 256>>>(ei);
    k_lhat1<<<Nn, 192>>>(x, lam);
    k_lhat2<<<Nn, 192>>>(x, lam);

    cudaFuncSetAttribute(k_fused, cudaFuncAttributeMaxDynamicSharedMemorySize,
                         SMEM_FLOATS * 4);
    // 148 blocks x 256 threads: 1 block/SM, 4 node-groups per block
    k_fused<<<148, 256, SMEM_FLOATS * 4>>>(x, chebW, chebB, timeW, timeB,
                                           resW, resB, gma, bta, out);
}